// round 7
// baseline (speedup 1.0000x reference)
#include <cuda_runtime.h>
#include <cuda_bf16.h>
#include <cstdint>

#define B_   256
#define T_   250
#define NIN  700
#define NHID 512
#define NOUT 20
#define KPAD 2816          // 4*NIN = 2800 padded to 128*22 (int8 bytes)
#define NSTG 22            // K stages of 128 bytes

// Quantization: A-blocks [x/6, t1, t2, t3] step 1/127; W-blocks [6*wk, d*] step SW.
#define SW_    (0.6f / 127.f)        // weight quant step (bound |wk|<=0.1)
#define SA_X   (127.f / 6.f)         // x -> q scale
#define WS0    (6.f / SW_)           // wk -> q scale (=1270)
#define WSD    (1.f / SW_)           // d  -> q scale (=211.67)
#define SFIN   (SW_ / 127.f)         // epilogue dequant scale

// ---------------- scratch (static __device__, no runtime alloc) -------------
__device__ float  g_iin[(size_t)B_ * T_ * NHID];   // [B*T][H] fp32
__device__ int8_t g_w8[(size_t)NHID * KPAD];       // [h][kk] s8, kk=4n+v
__device__ float  g_wrecT[NHID * NHID];            // w_rec^T
__device__ int    g_flag[B_];                      // per-batch spike flag

// ---------------- helpers ----------------------------------------------------
__device__ __forceinline__ uint32_t smem_u32(const void* p) {
    uint32_t a;
    asm("{ .reg .u64 t; cvta.to.shared.u64 t, %1; cvt.u32.u64 %0, t; }"
        : "=r"(a) : "l"(p));
    return a;
}
__device__ __forceinline__ uint32_t pack_s8_4(float f0, float f1, float f2, float f3) {
    int q0 = __float2int_rn(fminf(fmaxf(f0, -127.f), 127.f));
    int q1 = __float2int_rn(fminf(fmaxf(f1, -127.f), 127.f));
    int q2 = __float2int_rn(fminf(fmaxf(f2, -127.f), 127.f));
    int q3 = __float2int_rn(fminf(fmaxf(f3, -127.f), 127.f));
    uint32_t lo = __byte_perm((uint32_t)q0, (uint32_t)q1, 0x0040);
    uint32_t hi = __byte_perm((uint32_t)q2, (uint32_t)q3, 0x0040);
    return __byte_perm(lo, hi, 0x5410);   // bytes f0,f1,f2,f3 (k-ascending)
}
__device__ __forceinline__ void ldmx4(uint32_t* r, uint32_t addr) {
    asm volatile("ldmatrix.sync.aligned.m8n8.x4.shared.b16 {%0,%1,%2,%3}, [%4];"
                 : "=r"(r[0]), "=r"(r[1]), "=r"(r[2]), "=r"(r[3]) : "r"(addr));
}
__device__ __forceinline__ void mma_s8(int* c, const uint32_t* a,
                                       uint32_t b0, uint32_t b1) {
    asm volatile(
        "mma.sync.aligned.m16n8k32.row.col.s32.s8.s8.s32 "
        "{%0,%1,%2,%3}, {%4,%5,%6,%7}, {%8,%9}, {%0,%1,%2,%3};"
        : "+r"(c[0]), "+r"(c[1]), "+r"(c[2]), "+r"(c[3])
        : "r"(a[0]), "r"(a[1]), "r"(a[2]), "r"(a[3]), "r"(b0), "r"(b1));
}

// ---------------- prep kernels ----------------------------------------------
__global__ void prep_w8_kernel(const float* __restrict__ wk, const float* __restrict__ d1,
                               const float* __restrict__ d2, const float* __restrict__ d3) {
    int i = blockIdx.x * blockDim.x + threadIdx.x;
    if (i >= NHID * 704) return;
    int h = i / 704, n = i % 704;
    uint32_t w = 0;
    if (n < NIN)
        w = pack_s8_4(wk[h * NIN + n] * WS0, d1[h * NIN + n] * WSD,
                      d2[h * NIN + n] * WSD, d3[h * NIN + n] * WSD);
    *(uint32_t*)&g_w8[(size_t)h * KPAD + 4 * n] = w;
}
__global__ void prep_wrect_kernel(const float* __restrict__ wrec) {
    int i = blockIdx.x * blockDim.x + threadIdx.x;
    if (i < B_) g_flag[i] = 0;
    if (i >= NHID * NHID) return;
    int h = i % NHID, j = i / NHID;
    g_wrecT[j * NHID + h] = wrec[h * NHID + j];
}

// ---------------- GEMM: C[64000,512] = A'[.,KPAD] x B[512,KPAD]^T (s8) ------
// CTA 128x128, 8 warps (2M x 4N), warp tile 64x32. K staged 128 B, dbl-buffered.
// 128B rows => SW128 swizzle reduces to col ^ ((row & 7) << 4).
#define SMEM_A 0                    // 2 x 16384
#define SMEM_B 32768                // 2 x 16384
#define SM_TOT 65536

__global__ __launch_bounds__(256) void gemm_kernel(const float* __restrict__ x) {
    extern __shared__ char sm[];
    const uint32_t smb = smem_u32(sm);
    const int tid = threadIdx.x, lane = tid & 31, wid = tid >> 5;
    const int wm = wid >> 2, wn = wid & 3;
    const int m0 = blockIdx.y * 128, n0 = blockIdx.x * 128;

    // conversion/copy mapping: 2 threads per row, 64 kk-bytes each
    const int crow = tid >> 1;
    const int cgrp = tid & 1;
    const uint32_t cxor = (uint32_t)((crow & 7) << 4);

    // ldmatrix lane geometry (16-row x 32-byte blocks, 4 m8n8.b16 tiles)
    const int lrow = (lane & 7) | (((lane >> 3) & 1) << 3);   // 0..15
    const uint32_t lcolh = (uint32_t)((lane >> 4) << 4);      // 0 or 16
    const uint32_t lxor = (uint32_t)((lrow & 7) << 4);
    const uint32_t aoff0 = (uint32_t)((wm * 64 + lrow) * 128);
    const uint32_t boff0 = (uint32_t)((wn * 32 + lrow) * 128);

    int acc[4][4][4];
#pragma unroll
    for (int i = 0; i < 4; i++)
#pragma unroll
        for (int j = 0; j < 4; j++)
#pragma unroll
            for (int q = 0; q < 4; q++) acc[i][j][q] = 0;

    float xs[16];
    uint4 wv[4];

    auto load_stage = [&](int kb) {
        const int nb = kb * 32 + cgrp * 16;
#pragma unroll
        for (int jj = 0; jj < 4; jj++) {
            const int nb4 = nb + 4 * jj;
            if (nb4 + 4 <= NIN) {
                float4 v = __ldg((const float4*)(x + (size_t)(m0 + crow) * NIN + nb4));
                xs[4 * jj] = v.x; xs[4 * jj + 1] = v.y;
                xs[4 * jj + 2] = v.z; xs[4 * jj + 3] = v.w;
            } else {
                xs[4 * jj] = xs[4 * jj + 1] = xs[4 * jj + 2] = xs[4 * jj + 3] = 0.f;
            }
        }
        const int8_t* wsrc = g_w8 + (size_t)(n0 + crow) * KPAD + kb * 128 + cgrp * 64;
#pragma unroll
        for (int j = 0; j < 4; j++) wv[j] = __ldg((const uint4*)(wsrc + j * 16));
    };
    auto store_stage = [&](int slot) {
        char* ab = sm + SMEM_A + slot * 16384;
        char* bb = sm + SMEM_B + slot * 16384;
        uint32_t p[16];
#pragma unroll
        for (int i = 0; i < 16; i++) {
            float f = xs[i];
            float t1 = fminf(fabsf(f), 1.f);
            float T1 = t1 * 127.f;
            float T2 = T1 * t1;
            float T3 = T2 * t1;
            p[i] = pack_s8_4(f * SA_X, T1, T2, T3);
        }
#pragma unroll
        for (int j = 0; j < 4; j++) {
            uint32_t col = (uint32_t)(cgrp * 64 + j * 16);
            *(uint4*)(ab + crow * 128 + (col ^ cxor)) =
                make_uint4(p[4 * j], p[4 * j + 1], p[4 * j + 2], p[4 * j + 3]);
            *(uint4*)(bb + crow * 128 + (col ^ cxor)) = wv[j];
        }
    };

    load_stage(0);
    store_stage(0);

    for (int k = 0; k < NSTG; k++) {
        __syncthreads();
        const int p = k & 1;
        const bool hn = (k + 1 < NSTG);
        if (hn) load_stage(k + 1);

        const uint32_t abuf = smb + SMEM_A + p * 16384;
        const uint32_t bbuf = smb + SMEM_B + p * 16384;
#pragma unroll
        for (int ks = 0; ks < 4; ks++) {
            uint32_t af[4][4], bf[2][4];
            const uint32_t klow = ((uint32_t)(ks * 32) + lcolh) ^ lxor;
#pragma unroll
            for (int mt = 0; mt < 4; mt++)
                ldmx4(af[mt], abuf + aoff0 + (uint32_t)(mt * 2048) + klow);
#pragma unroll
            for (int q = 0; q < 2; q++)
                ldmx4(bf[q], bbuf + boff0 + (uint32_t)(q * 2048) + klow);
            // bf[q]: r0=b0(n-grp0) r1=b0(n-grp1) r2=b1(n-grp0) r3=b1(n-grp1)
#pragma unroll
            for (int mt = 0; mt < 4; mt++)
#pragma unroll
                for (int nt = 0; nt < 4; nt++)
                    mma_s8(acc[mt][nt], af[mt],
                           bf[nt >> 1][nt & 1], bf[nt >> 1][(nt & 1) + 2]);
        }
        if (hn) store_stage(p ^ 1);
    }

    // ---- epilogue (dequantize) ---------------------------------------------
    const float S = SFIN;
#pragma unroll
    for (int mt = 0; mt < 4; mt++) {
        const int r0 = m0 + wm * 64 + mt * 16 + (lane >> 2);
#pragma unroll
        for (int nt = 0; nt < 4; nt++) {
            const int col = n0 + wn * 32 + nt * 8 + 2 * (lane & 3);
            *(float2*)&g_iin[(size_t)r0 * NHID + col] =
                make_float2(S * (float)acc[mt][nt][0], S * (float)acc[mt][nt][1]);
            *(float2*)&g_iin[(size_t)(r0 + 8) * NHID + col] =
                make_float2(S * (float)acc[mt][nt][2], S * (float)acc[mt][nt][3]);
        }
    }
}

// ---------------- spike-free detection (barrier-free, full occupancy) --------
// Before the first spike, hidden dynamics are exactly per-(b,h) independent
// (s==0, a==0, threshold==1). A spike exists iff max_t v_t > 1 for some h.
__global__ __launch_bounds__(256) void detect_kernel() {
    const int g = blockIdx.x * 256 + threadIdx.x;   // 0 .. B_*NHID-1
    const int b = g >> 9, h = g & (NHID - 1);
    const float* iin = g_iin + (size_t)b * T_ * NHID + h;
    float v = 0.f, vmax = -1.f;
#pragma unroll 10
    for (int t = 0; t < T_; t++) {
        v = 0.95f * v + 0.05f * iin[(size_t)t * NHID];
        vmax = fmaxf(vmax, v);
    }
    if (vmax > 1.0f) atomicExch(&g_flag[b], 1);
}

// ---------------- scan: 1 CTA / batch (heavy path only when flagged) --------
__global__ __launch_bounds__(512) void scan_kernel(const float* __restrict__ w_out,
                                                   float* __restrict__ out) {
    const int b = blockIdx.x, h = threadIdx.x;

    if (g_flag[b] == 0) {   // spike-free: i_out==0 forever -> output exactly 0
        if (h < NOUT) out[b * NOUT + h] = 0.f;
        return;
    }

    const int warp = h >> 5, lane = h & 31;
    __shared__ int s_idx[NHID];
    __shared__ unsigned s_mask[16];

    float v = 0.f, a = 0.f, sprev = 0.f, vout = 0.f, accum = 0.f;
    int cnt = 0;
    const float* iin = g_iin + (size_t)b * T_ * NHID + h;
    float c[8];
#pragma unroll
    for (int j = 0; j < 8; j++) c[j] = iin[(size_t)j * NHID];

    for (int t = 0; t < T_; t++) {
        float i1 = c[0];
#pragma unroll
        for (int j = 0; j < 7; j++) c[j] = c[j + 1];
        c[7] = (t + 8 < T_) ? iin[(size_t)(t + 8) * NHID] : 0.f;

        for (int k = 0; k < cnt; k++) i1 += g_wrecT[s_idx[k] * NHID + h];

        v = 0.95f * v + 0.05f * i1 - sprev;
        a = 0.85f * a + 0.15f * sprev;
        const bool spk = (v - (1.0f + 0.05f * a)) > 0.f;

        const int total = __syncthreads_count((int)spk);
        if (total) {  // deterministic compaction of active indices
            const unsigned m = __ballot_sync(0xffffffffu, spk);
            if (lane == 0) s_mask[warp] = m;
            __syncthreads();
            int base = 0;
#pragma unroll
            for (int w = 0; w < 16; w++)
                if (w < warp) base += __popc(s_mask[w]);
            if (spk) s_idx[base + __popc(m & ((1u << lane) - 1u))] = h;
            __syncthreads();
        }

        if (h < NOUT) {
            float io = 0.f;
            for (int k = 0; k < total; k++) io += w_out[h * NHID + s_idx[k]];
            vout = 0.9f * vout + io;
            const float so = vout > 1.f ? 1.f : 0.f;
            vout -= so;
            accum += vout;
        }
        sprev = spk ? 1.f : 0.f;
        cnt = total;
    }
    if (h < NOUT) out[b * NOUT + h] = accum * (1.0f / (float)T_);
}

// ---------------------------------------------------------------------------
extern "C" void kernel_launch(void* const* d_in, const int* in_sizes, int n_in,
                              void* d_out, int out_size) {
    const float* x     = (const float*)d_in[0];
    const float* w_kan = (const float*)d_in[1];
    const float* d1    = (const float*)d_in[2];
    const float* d2    = (const float*)d_in[3];
    const float* d3    = (const float*)d_in[4];
    const float* w_rec = (const float*)d_in[5];
    const float* w_out = (const float*)d_in[6];
    float* out = (float*)d_out;

    cudaFuncSetAttribute(gemm_kernel, cudaFuncAttributeMaxDynamicSharedMemorySize, SM_TOT);

    prep_w8_kernel<<<(NHID * 704 + 255) / 256, 256>>>(w_kan, d1, d2, d3);
    prep_wrect_kernel<<<(NHID * NHID + 255) / 256, 256>>>(w_rec);

    dim3 grid(NHID / 128, (B_ * T_) / 128);  // (4, 500)
    gemm_kernel<<<grid, 256, SM_TOT>>>(x);

    detect_kernel<<<(B_ * NHID) / 256, 256>>>();
    scan_kernel<<<B_, NHID>>>(w_out, out);
}

// round 9
// speedup vs baseline: 1.7773x; 1.7773x over previous
#include <cuda_runtime.h>
#include <cuda_bf16.h>
#include <cuda_fp16.h>
#include <cstdint>

#define B_   256
#define T_   250
#define NIN  700
#define NHID 512
#define NOUT 20
#define KPAD 2816          // 4*NIN = 2800 padded to 128*22 (fp8 bytes)
#define NSTG 22            // K stages of 128 bytes
#define WSCALE 64.0f       // weight pre-scale into e4m3 normal range

// ---------------- scratch (static __device__, no runtime alloc) -------------
__device__ float   g_iin[(size_t)B_ * T_ * NHID];   // [B*T][H] fp32
__device__ uint8_t g_w8[(size_t)NHID * KPAD];       // [h][kk] e4m3, kk=4n+v
__device__ float   g_wrecT[NHID * NHID];            // w_rec^T
__device__ int     g_flag[B_];                      // per-batch spike flag

// ---------------- helpers ----------------------------------------------------
__device__ __forceinline__ uint32_t smem_u32(const void* p) {
    uint32_t a;
    asm("{ .reg .u64 t; cvta.to.shared.u64 t, %1; cvt.u32.u64 %0, t; }"
        : "=r"(a) : "l"(p));
    return a;
}
__device__ __forceinline__ uint32_t pack_e4m3_4(float f0, float f1, float f2, float f3) {
    uint16_t lo, hi;  // d<7:0> = cvt(src2), d<15:8> = cvt(src1)
    asm("cvt.rn.satfinite.e4m3x2.f32 %0, %1, %2;" : "=h"(lo) : "f"(f1), "f"(f0));
    asm("cvt.rn.satfinite.e4m3x2.f32 %0, %1, %2;" : "=h"(hi) : "f"(f3), "f"(f2));
    return (uint32_t)lo | ((uint32_t)hi << 16);   // bytes f0,f1,f2,f3 (k-ascending)
}
__device__ __forceinline__ void ldmx4(uint32_t* r, uint32_t addr) {
    asm volatile("ldmatrix.sync.aligned.m8n8.x4.shared.b16 {%0,%1,%2,%3}, [%4];"
                 : "=r"(r[0]), "=r"(r[1]), "=r"(r[2]), "=r"(r[3]) : "r"(addr));
}
// fp8 x fp8 -> f16 accumulator (2 c-regs). Testing whether f16-acc doubles the
// fallback tensor rate vs the f32-acc variant.
__device__ __forceinline__ void mma_e4m3_h(uint32_t* c, const uint32_t* a,
                                           uint32_t b0, uint32_t b1) {
    asm volatile(
        "mma.sync.aligned.m16n8k32.row.col.f16.e4m3.e4m3.f16 "
        "{%0,%1}, {%2,%3,%4,%5}, {%6,%7}, {%0,%1};"
        : "+r"(c[0]), "+r"(c[1])
        : "r"(a[0]), "r"(a[1]), "r"(a[2]), "r"(a[3]), "r"(b0), "r"(b1));
}

// ---------------- prep kernels ----------------------------------------------
__global__ void prep_w8_kernel(const float* __restrict__ wk, const float* __restrict__ d1,
                               const float* __restrict__ d2, const float* __restrict__ d3) {
    int i = blockIdx.x * blockDim.x + threadIdx.x;
    if (i >= NHID * 704) return;
    int h = i / 704, n = i % 704;
    uint32_t w = 0;
    if (n < NIN)
        w = pack_e4m3_4(wk[h * NIN + n] * WSCALE, d1[h * NIN + n] * WSCALE,
                        d2[h * NIN + n] * WSCALE, d3[h * NIN + n] * WSCALE);
    *(uint32_t*)&g_w8[(size_t)h * KPAD + 4 * n] = w;
}
__global__ void prep_wrect_kernel(const float* __restrict__ wrec) {
    int i = blockIdx.x * blockDim.x + threadIdx.x;
    if (i < B_) g_flag[i] = 0;
    if (i >= NHID * NHID) return;
    int h = i % NHID, j = i / NHID;
    g_wrecT[j * NHID + h] = wrec[h * NHID + j];
}

// ---------------- GEMM: C[64000,512] = A'[.,KPAD] x B[512,KPAD]^T (e4m3) ----
// CTA 128x128, 8 warps (2M x 4N), warp tile 64x32. K staged 128 B, dbl-buffered.
// f16 accumulators, split into two K-halves (stages 0-10 / 11-21), summed fp32.
// 128B rows => SW128 swizzle reduces to col ^ ((row & 7) << 4).
#define SMEM_A 0                    // 2 x 16384
#define SMEM_B 32768                // 2 x 16384
#define SM_TOT 65536

__global__ __launch_bounds__(256) void gemm_kernel(const float* __restrict__ x) {
    extern __shared__ char sm[];
    const uint32_t smb = smem_u32(sm);
    const int tid = threadIdx.x, lane = tid & 31, wid = tid >> 5;
    const int wm = wid >> 2, wn = wid & 3;
    const int m0 = blockIdx.y * 128, n0 = blockIdx.x * 128;

    // conversion/copy mapping: 2 threads per row, 64 kk-bytes each
    const int crow = tid >> 1;
    const int cgrp = tid & 1;
    const uint32_t cxor = (uint32_t)((crow & 7) << 4);

    // ldmatrix lane geometry (16-row x 32-byte blocks, 4 m8n8.b16 tiles)
    const int lrow = (lane & 7) | (((lane >> 3) & 1) << 3);   // 0..15
    const uint32_t lcolh = (uint32_t)((lane >> 4) << 4);      // 0 or 16
    const uint32_t lxor = (uint32_t)((lrow & 7) << 4);
    const uint32_t aoff0 = (uint32_t)((wm * 64 + lrow) * 128);
    const uint32_t boff0 = (uint32_t)((wn * 32 + lrow) * 128);

    uint32_t acc[2][4][4][2];       // [kset][mt][nt][creg], f16x2 each
#pragma unroll
    for (int s = 0; s < 2; s++)
#pragma unroll
        for (int i = 0; i < 4; i++)
#pragma unroll
            for (int j = 0; j < 4; j++) { acc[s][i][j][0] = 0u; acc[s][i][j][1] = 0u; }

    float xs[16];
    uint4 wv[4];

    auto load_stage = [&](int kb) {
        const int nb = kb * 32 + cgrp * 16;
#pragma unroll
        for (int jj = 0; jj < 4; jj++) {
            const int nb4 = nb + 4 * jj;
            if (nb4 + 4 <= NIN) {
                float4 v = __ldg((const float4*)(x + (size_t)(m0 + crow) * NIN + nb4));
                xs[4 * jj] = v.x; xs[4 * jj + 1] = v.y;
                xs[4 * jj + 2] = v.z; xs[4 * jj + 3] = v.w;
            } else {
                xs[4 * jj] = xs[4 * jj + 1] = xs[4 * jj + 2] = xs[4 * jj + 3] = 0.f;
            }
        }
        const uint8_t* wsrc = g_w8 + (size_t)(n0 + crow) * KPAD + kb * 128 + cgrp * 64;
#pragma unroll
        for (int j = 0; j < 4; j++) wv[j] = __ldg((const uint4*)(wsrc + j * 16));
    };
    auto store_stage = [&](int slot) {
        char* ab = sm + SMEM_A + slot * 16384;
        char* bb = sm + SMEM_B + slot * 16384;
        uint32_t p[16];
#pragma unroll
        for (int i = 0; i < 16; i++) {
            float f = xs[i];
            float t1 = fminf(fabsf(f), 1.f);
            float t2 = t1 * t1, t3 = t2 * t1;
            p[i] = pack_e4m3_4(f, t1, t2, t3);
        }
#pragma unroll
        for (int j = 0; j < 4; j++) {
            uint32_t col = (uint32_t)(cgrp * 64 + j * 16);
            *(uint4*)(ab + crow * 128 + (col ^ cxor)) =
                make_uint4(p[4 * j], p[4 * j + 1], p[4 * j + 2], p[4 * j + 3]);
            *(uint4*)(bb + crow * 128 + (col ^ cxor)) = wv[j];
        }
    };

    load_stage(0);
    store_stage(0);

    for (int k = 0; k < NSTG; k++) {
        __syncthreads();
        const int p = k & 1;
        const int kset = (k < 11) ? 0 : 1;
        const bool hn = (k + 1 < NSTG);
        if (hn) load_stage(k + 1);

        const uint32_t abuf = smb + SMEM_A + p * 16384;
        const uint32_t bbuf = smb + SMEM_B + p * 16384;
#pragma unroll
        for (int ks = 0; ks < 4; ks++) {
            uint32_t af[4][4], bf[2][4];
            const uint32_t klow = ((uint32_t)(ks * 32) + lcolh) ^ lxor;
#pragma unroll
            for (int mt = 0; mt < 4; mt++)
                ldmx4(af[mt], abuf + aoff0 + (uint32_t)(mt * 2048) + klow);
#pragma unroll
            for (int q = 0; q < 2; q++)
                ldmx4(bf[q], bbuf + boff0 + (uint32_t)(q * 2048) + klow);
            // bf[q]: r0=b0(n-grp0) r1=b0(n-grp1) r2=b1(n-grp0) r3=b1(n-grp1)
#pragma unroll
            for (int mt = 0; mt < 4; mt++)
#pragma unroll
                for (int nt = 0; nt < 4; nt++)
                    mma_e4m3_h(acc[kset][mt][nt], af[mt],
                               bf[nt >> 1][nt & 1], bf[nt >> 1][(nt & 1) + 2]);
        }
        if (hn) store_stage(p ^ 1);
    }

    // ---- epilogue: sum the two f16 K-halves in fp32, undo weight scale -----
    const float inv = 1.0f / WSCALE;
#pragma unroll
    for (int mt = 0; mt < 4; mt++) {
        const int r0 = m0 + wm * 64 + mt * 16 + (lane >> 2);
#pragma unroll
        for (int nt = 0; nt < 4; nt++) {
            const int col = n0 + wn * 32 + nt * 8 + 2 * (lane & 3);
            float2 a0 = __half22float2(*(__half2*)&acc[0][mt][nt][0]);
            float2 b0 = __half22float2(*(__half2*)&acc[1][mt][nt][0]);
            float2 a1 = __half22float2(*(__half2*)&acc[0][mt][nt][1]);
            float2 b1 = __half22float2(*(__half2*)&acc[1][mt][nt][1]);
            *(float2*)&g_iin[(size_t)r0 * NHID + col] =
                make_float2((a0.x + b0.x) * inv, (a0.y + b0.y) * inv);
            *(float2*)&g_iin[(size_t)(r0 + 8) * NHID + col] =
                make_float2((a1.x + b1.x) * inv, (a1.y + b1.y) * inv);
        }
    }
}

// ---------------- spike-free detection (barrier-free, full occupancy) --------
// Before the first spike, hidden dynamics are exactly per-(b,h) independent
// (s==0, a==0, threshold==1). A spike exists iff max_t v_t > 1 for some h.
__global__ __launch_bounds__(256) void detect_kernel() {
    const int g = blockIdx.x * 256 + threadIdx.x;   // 0 .. B_*NHID-1
    const int b = g >> 9, h = g & (NHID - 1);
    const float* iin = g_iin + (size_t)b * T_ * NHID + h;
    float v = 0.f, vmax = -1.f;
#pragma unroll 10
    for (int t = 0; t < T_; t++) {
        v = 0.95f * v + 0.05f * iin[(size_t)t * NHID];
        vmax = fmaxf(vmax, v);
    }
    if (vmax > 1.0f) atomicExch(&g_flag[b], 1);
}

// ---------------- scan: 1 CTA / batch (heavy path only when flagged) --------
__global__ __launch_bounds__(512) void scan_kernel(const float* __restrict__ w_out,
                                                   float* __restrict__ out) {
    const int b = blockIdx.x, h = threadIdx.x;

    if (g_flag[b] == 0) {   // spike-free: i_out==0 forever -> output exactly 0
        if (h < NOUT) out[b * NOUT + h] = 0.f;
        return;
    }

    const int warp = h >> 5, lane = h & 31;
    __shared__ int s_idx[NHID];
    __shared__ unsigned s_mask[16];

    float v = 0.f, a = 0.f, sprev = 0.f, vout = 0.f, accum = 0.f;
    int cnt = 0;
    const float* iin = g_iin + (size_t)b * T_ * NHID + h;
    float c[8];
#pragma unroll
    for (int j = 0; j < 8; j++) c[j] = iin[(size_t)j * NHID];

    for (int t = 0; t < T_; t++) {
        float i1 = c[0];
#pragma unroll
        for (int j = 0; j < 7; j++) c[j] = c[j + 1];
        c[7] = (t + 8 < T_) ? iin[(size_t)(t + 8) * NHID] : 0.f;

        for (int k = 0; k < cnt; k++) i1 += g_wrecT[s_idx[k] * NHID + h];

        v = 0.95f * v + 0.05f * i1 - sprev;
        a = 0.85f * a + 0.15f * sprev;
        const bool spk = (v - (1.0f + 0.05f * a)) > 0.f;

        const int total = __syncthreads_count((int)spk);
        if (total) {  // deterministic compaction of active indices
            const unsigned m = __ballot_sync(0xffffffffu, spk);
            if (lane == 0) s_mask[warp] = m;
            __syncthreads();
            int base = 0;
#pragma unroll
            for (int w = 0; w < 16; w++)
                if (w < warp) base += __popc(s_mask[w]);
            if (spk) s_idx[base + __popc(m & ((1u << lane) - 1u))] = h;
            __syncthreads();
        }

        if (h < NOUT) {
            float io = 0.f;
            for (int k = 0; k < total; k++) io += w_out[h * NHID + s_idx[k]];
            vout = 0.9f * vout + io;
            const float so = vout > 1.f ? 1.f : 0.f;
            vout -= so;
            accum += vout;
        }
        sprev = spk ? 1.f : 0.f;
        cnt = total;
    }
    if (h < NOUT) out[b * NOUT + h] = accum * (1.0f / (float)T_);
}

// ---------------------------------------------------------------------------
extern "C" void kernel_launch(void* const* d_in, const int* in_sizes, int n_in,
                              void* d_out, int out_size) {
    const float* x     = (const float*)d_in[0];
    const float* w_kan = (const float*)d_in[1];
    const float* d1    = (const float*)d_in[2];
    const float* d2    = (const float*)d_in[3];
    const float* d3    = (const float*)d_in[4];
    const float* w_rec = (const float*)d_in[5];
    const float* w_out = (const float*)d_in[6];
    float* out = (float*)d_out;

    cudaFuncSetAttribute(gemm_kernel, cudaFuncAttributeMaxDynamicSharedMemorySize, SM_TOT);

    prep_w8_kernel<<<(NHID * 704 + 255) / 256, 256>>>(w_kan, d1, d2, d3);
    prep_wrect_kernel<<<(NHID * NHID + 255) / 256, 256>>>(w_rec);

    dim3 grid(NHID / 128, (B_ * T_) / 128);  // (4, 500)
    gemm_kernel<<<grid, 256, SM_TOT>>>(x);

    detect_kernel<<<(B_ * NHID) / 256, 256>>>();
    scan_kernel<<<B_, NHID>>>(w_out, out);
}